// round 12
// baseline (speedup 1.0000x reference)
#include <cuda_runtime.h>
#include <math.h>

#define T_LEN 256
#define BATCH 512
#define ADIM 32
#define ZDIM 16
#define HID 128
#define G4 512
#define TB (T_LEN*BATCH)

static constexpr long long SZ_MEANS = (long long)TB * ZDIM;
static constexpr long long SZ_COVS  = (long long)TB * ZDIM * ZDIM;
static constexpr long long SZ_AS    = (long long)(T_LEN+1) * BATCH * ZDIM * ZDIM;
static constexpr long long SZ_CS    = (long long)(T_LEN+1) * BATCH * ADIM * ZDIM;
static constexpr long long OFF_MEANS = 0;
static constexpr long long OFF_COVS  = OFF_MEANS + SZ_MEANS;
static constexpr long long OFF_NM    = OFF_COVS + SZ_COVS;
static constexpr long long OFF_NC    = OFF_NM + SZ_MEANS;
static constexpr long long OFF_AS    = OFF_NC + SZ_COVS;
static constexpr long long OFF_CS    = OFF_AS + SZ_AS;

__device__ float g_gates0[(size_t)TB * G4];
__device__ float g_h1all[(size_t)TB * HID];
__device__ float g_h0buf[2][BATCH * HID];
__device__ float g_h1buf[2][BATCH * HID];
__device__ float g_c0[BATCH * HID];
__device__ float g_c1[BATCH * HID];
__device__ float g_W0i[G4 * ADIM];
__device__ float g_W0h[G4 * HID];
__device__ float g_W1c[G4 * 2 * HID];
__device__ float g_b0[G4];
__device__ float g_b1[G4];
__device__ float g_wall[(T_LEN + 1) * BATCH * 3];
__device__ float g_Q[ZDIM * ZDIM];
__device__ float g_R[ADIM * ADIM];

__global__ void prep_kernel(const float* __restrict__ QL, const float* __restrict__ RL,
                            const float* __restrict__ Wih0, const float* __restrict__ Whh0,
                            const float* __restrict__ bih0, const float* __restrict__ bhh0,
                            const float* __restrict__ Wih1, const float* __restrict__ Whh1,
                            const float* __restrict__ bih1, const float* __restrict__ bhh1)
{
    int gid = blockIdx.x * blockDim.x + threadIdx.x;
    int gsz = gridDim.x * blockDim.x;
    for (int i = gid; i < G4 * ADIM; i += gsz) {
        int rr = i / ADIM, k = i % ADIM, j = rr >> 2, g = rr & 3;
        g_W0i[i] = Wih0[(g * HID + j) * ADIM + k];
    }
    for (int i = gid; i < G4 * HID; i += gsz) {
        int rr = i / HID, k = i % HID, j = rr >> 2, g = rr & 3;
        g_W0h[i] = Whh0[(g * HID + j) * HID + k];
    }
    for (int i = gid; i < G4 * 2 * HID; i += gsz) {
        int rr = i / (2 * HID), k = i % (2 * HID), j = rr >> 2, g = rr & 3;
        int src = g * HID + j;
        g_W1c[i] = (k < HID) ? Wih1[src * HID + k] : Whh1[src * HID + (k - HID)];
    }
    for (int i = gid; i < G4; i += gsz) {
        int j = i >> 2, g = i & 3, s = g * HID + j;
        g_b0[i] = bih0[s] + bhh0[s];
        g_b1[i] = bih1[s] + bhh1[s];
    }
    for (int i = gid; i < BATCH * HID; i += gsz) {
        g_h0buf[0][i] = 0.f; g_h0buf[1][i] = 0.f;
        g_h1buf[0][i] = 0.f; g_h1buf[1][i] = 0.f;
        g_c0[i] = 0.f; g_c1[i] = 0.f;
    }
    for (int i = gid; i < BATCH * 3; i += gsz) g_wall[i] = 1.0f;
    for (int i = gid; i < ZDIM * ZDIM; i += gsz) {
        int r = i >> 4, c = i & 15;
        float s = (r == c) ? 1e-3f : 0.f;
        for (int k = 0; k < ZDIM; k++) s += QL[r * ZDIM + k] * QL[c * ZDIM + k];
        g_Q[i] = s;
    }
    for (int i = gid; i < ADIM * ADIM; i += gsz) {
        int r = i >> 5, c = i & 31;
        float s = (r == c) ? 1e-3f : 0.f;
        for (int k = 0; k < ADIM; k++) s += RL[r * ADIM + k] * RL[c * ADIM + k];
        g_R[i] = s;
    }
}

// bulk: g_gates0[row, :] = bias + x[row,:] @ W0i^T   (row = t*B+b)
__global__ void input_gemm0(const float* __restrict__ x)
{
    __shared__ float Xs[64][33];
    __shared__ float Ws[128][33];
    int tid = threadIdx.x;
    int row0 = blockIdx.x * 64;
    for (int e = tid; e < 64 * 32; e += 256) {
        int r = e >> 5, c = e & 31;
        Xs[r][c] = x[(size_t)(row0 + r) * ADIM + c];
    }
    int ty = tid >> 4, tx = tid & 15;
    for (int cc0 = 0; cc0 < G4; cc0 += 128) {
        __syncthreads();
        for (int e = tid; e < 128 * 32; e += 256) {
            int r = e >> 5, c = e & 31;
            Ws[r][c] = g_W0i[(size_t)(cc0 + r) * ADIM + c];
        }
        __syncthreads();
        float acc[4][8];
#pragma unroll
        for (int rr = 0; rr < 4; rr++)
#pragma unroll
            for (int cc = 0; cc < 8; cc++) acc[rr][cc] = 0.f;
#pragma unroll
        for (int kk = 0; kk < 32; kk++) {
            float a[4], b[8];
#pragma unroll
            for (int rr = 0; rr < 4; rr++) a[rr] = Xs[ty * 4 + rr][kk];
#pragma unroll
            for (int cc = 0; cc < 8; cc++) b[cc] = Ws[tx * 8 + cc][kk];
#pragma unroll
            for (int rr = 0; rr < 4; rr++)
#pragma unroll
                for (int cc = 0; cc < 8; cc++) acc[rr][cc] += a[rr] * b[cc];
        }
#pragma unroll
        for (int rr = 0; rr < 4; rr++) {
            size_t base = (size_t)(row0 + ty * 4 + rr) * G4 + cc0 + tx * 8;
#pragma unroll
            for (int cc = 0; cc < 8; cc++)
                g_gates0[base + cc] = acc[rr][cc] + g_b0[cc0 + tx * 8 + cc];
        }
    }
}

// blocks [0,64): layer0 step k ; blocks [64,192): layer1 step k-1
__global__ void lstm_step(int k)
{
    int bid = blockIdx.x;
    int tid = threadIdx.x;
    if (bid < 64) {
        if (k >= T_LEN) return;
        __shared__ float Hs[64][33];
        __shared__ float Ws[64][33];
        int row0 = (bid >> 3) * 64, col0 = (bid & 7) * 64;
        const float* __restrict__ hprev = g_h0buf[(k & 1) ^ 1];
        float* __restrict__ hout = g_h0buf[k & 1];
        int ty = tid >> 4, tx = tid & 15;
        float acc[4][4];
#pragma unroll
        for (int rr = 0; rr < 4; rr++) {
            size_t base = ((size_t)k * BATCH + row0 + ty * 4 + rr) * G4 + col0 + tx * 4;
#pragma unroll
            for (int cc = 0; cc < 4; cc++) acc[rr][cc] = g_gates0[base + cc];
        }
        for (int kc = 0; kc < HID; kc += 32) {
            __syncthreads();
            for (int e = tid; e < 64 * 32; e += 256) {
                int r = e >> 5, c = e & 31;
                Hs[r][c] = hprev[(row0 + r) * HID + kc + c];
                Ws[r][c] = g_W0h[(size_t)(col0 + r) * HID + kc + c];
            }
            __syncthreads();
#pragma unroll
            for (int kk = 0; kk < 32; kk++) {
                float a[4], b[4];
#pragma unroll
                for (int rr = 0; rr < 4; rr++) a[rr] = Hs[ty * 4 + rr][kk];
#pragma unroll
                for (int cc = 0; cc < 4; cc++) b[cc] = Ws[tx * 4 + cc][kk];
#pragma unroll
                for (int rr = 0; rr < 4; rr++)
#pragma unroll
                    for (int cc = 0; cc < 4; cc++) acc[rr][cc] += a[rr] * b[cc];
            }
        }
        int j = (col0 >> 2) + tx;  // col0/4 + tx : hidden index
#pragma unroll
        for (int rr = 0; rr < 4; rr++) {
            int bb = row0 + ty * 4 + rr;
            float ig = 1.f / (1.f + expf(-acc[rr][0]));
            float fg = 1.f / (1.f + expf(-acc[rr][1]));
            float gg = tanhf(acc[rr][2]);
            float og = 1.f / (1.f + expf(-acc[rr][3]));
            float c = fg * g_c0[bb * HID + j] + ig * gg;
            g_c0[bb * HID + j] = c;
            hout[bb * HID + j] = og * tanhf(c);
        }
    } else {
        if (k < 1) return;
        int b2 = bid - 64;
        int row0 = (b2 >> 3) * 32, col0 = (b2 & 7) * 64;
        int t1 = k - 1;
        const float* __restrict__ h0in = g_h0buf[t1 & 1];
        const float* __restrict__ h1in = g_h1buf[(t1 & 1) ^ 1];
        float* __restrict__ h1out = g_h1buf[t1 & 1];
        __shared__ float Hs1[32][33];
        __shared__ float Ws1[64][33];
        int ty = tid >> 4, tx = tid & 15;
        float acc[2][4];
#pragma unroll
        for (int rr = 0; rr < 2; rr++)
#pragma unroll
            for (int cc = 0; cc < 4; cc++) acc[rr][cc] = g_b1[col0 + tx * 4 + cc];
        for (int kc = 0; kc < 2 * HID; kc += 32) {
            __syncthreads();
            const float* __restrict__ src = (kc < HID) ? h0in : h1in;
            int koff = (kc < HID) ? kc : kc - HID;
            for (int e = tid; e < 32 * 32; e += 256) {
                int r = e >> 5, c = e & 31;
                Hs1[r][c] = src[(row0 + r) * HID + koff + c];
            }
            for (int e = tid; e < 64 * 32; e += 256) {
                int r = e >> 5, c = e & 31;
                Ws1[r][c] = g_W1c[(size_t)(col0 + r) * (2 * HID) + kc + c];
            }
            __syncthreads();
#pragma unroll
            for (int kk = 0; kk < 32; kk++) {
                float a[2], b[4];
#pragma unroll
                for (int rr = 0; rr < 2; rr++) a[rr] = Hs1[ty * 2 + rr][kk];
#pragma unroll
                for (int cc = 0; cc < 4; cc++) b[cc] = Ws1[tx * 4 + cc][kk];
#pragma unroll
                for (int rr = 0; rr < 2; rr++)
#pragma unroll
                    for (int cc = 0; cc < 4; cc++) acc[rr][cc] += a[rr] * b[cc];
            }
        }
        int j = (col0 >> 2) + tx;
#pragma unroll
        for (int rr = 0; rr < 2; rr++) {
            int bb = row0 + ty * 2 + rr;
            float ig = 1.f / (1.f + expf(-acc[rr][0]));
            float fg = 1.f / (1.f + expf(-acc[rr][1]));
            float gg = tanhf(acc[rr][2]);
            float og = 1.f / (1.f + expf(-acc[rr][3]));
            float c = fg * g_c1[bb * HID + j] + ig * gg;
            g_c1[bb * HID + j] = c;
            float h = og * tanhf(c);
            h1out[bb * HID + j] = h;
            g_h1all[((size_t)t1 * BATCH + bb) * HID + j] = h;
        }
    }
}

__global__ void logits_kernel(const float* __restrict__ Wlin, const float* __restrict__ blin)
{
    int row = blockIdx.x * 4 + (threadIdx.x >> 5);
    int lane = threadIdx.x & 31;
    const float* h = g_h1all + (size_t)row * HID;
    float v0 = h[lane], v1 = h[lane + 32], v2 = h[lane + 64], v3 = h[lane + 96];
    float lg[3];
#pragma unroll
    for (int kk = 0; kk < 3; kk++) {
        const float* w = Wlin + kk * HID;
        float d = v0 * w[lane] + v1 * w[lane + 32] + v2 * w[lane + 64] + v3 * w[lane + 96];
#pragma unroll
        for (int off = 16; off > 0; off >>= 1) d += __shfl_xor_sync(0xffffffffu, d, off);
        lg[kk] = d + blin[kk];
    }
    if (lane == 0) {
        float m = fmaxf(lg[0], fmaxf(lg[1], lg[2]));
        float e0 = expf(lg[0] - m), e1 = expf(lg[1] - m), e2 = expf(lg[2] - m);
        float s = 1.f / (e0 + e1 + e2);
        float* w = g_wall + ((size_t)row + BATCH) * 3;
        w[0] = e0 * s; w[1] = e1 * s; w[2] = e2 * s;
    }
}

__global__ void einsum_kernel(const float* __restrict__ AK, const float* __restrict__ CK,
                              float* __restrict__ out)
{
    long long NTOT = SZ_AS + SZ_CS;
    long long stride = (long long)gridDim.x * blockDim.x;
    for (long long idx = (long long)blockIdx.x * blockDim.x + threadIdx.x; idx < NTOT; idx += stride) {
        if (idx < SZ_AS) {
            long long row = idx >> 8;
            int ij = (int)(idx & 255);
            const float* w = g_wall + row * 3;
            out[OFF_AS + idx] = w[0] * AK[ij] + w[1] * AK[256 + ij] + w[2] * AK[512 + ij];
        } else {
            long long i2 = idx - SZ_AS;
            long long row = i2 >> 9;
            int ij = (int)(i2 & 511);
            const float* w = g_wall + row * 3;
            out[OFF_CS + i2] = w[0] * CK[ij] + w[1] * CK[512 + ij] + w[2] * CK[1024 + ij];
        }
    }
}

// one block per batch element; 256 Kalman steps in-block
__global__ void __launch_bounds__(128) kalman_kernel(
    const float* __restrict__ as_, const float* __restrict__ init_mean,
    const float* __restrict__ init_cov, float* __restrict__ out)
{
    __shared__ float sP[16][17], sPf[16][17], sPp[16][17], sTmp[16][17];
    __shared__ float sA[16][17], sQ[16][17];
    __shared__ float sC[32][17], CPo[32][17];
    __shared__ float aug[32][51];         // [S(32) | X(16) | y(1)] + pad
    __shared__ float sR[32][33];
    __shared__ float colk[32], rowk[49], sm_[16], smf[16];
    __shared__ float s_pinv;

    int b = blockIdx.x;
    int tid = threadIdx.x;

    for (int e = tid; e < 256; e += 128) {
        sP[e >> 4][e & 15] = init_cov[e];
        sQ[e >> 4][e & 15] = g_Q[e];
    }
    for (int e = tid; e < 1024; e += 128) sR[e >> 5][e & 31] = g_R[e];
    if (tid < 16) sm_[tid] = init_mean[tid];
    __syncthreads();

    for (int t = 0; t < T_LEN; t++) {
        // load C_t, A_{t+1}, a_t
        for (int e = tid; e < 512; e += 128)
            sC[e >> 4][e & 15] = out[OFF_CS + ((long long)t * BATCH + b) * 512 + e];
        for (int e = tid; e < 256; e += 128)
            sA[e >> 4][e & 15] = out[OFF_AS + ((long long)(t + 1) * BATCH + b) * 256 + e];
        __syncthreads();

        // CPo = C @ P  (32x16)
        for (int e = tid; e < 512; e += 128) {
            int r = e >> 4, c = e & 15;
            float s = 0.f;
#pragma unroll
            for (int kk = 0; kk < 16; kk++) s += sC[r][kk] * sP[kk][c];
            CPo[r][c] = s;
            aug[r][32 + c] = s;
        }
        __syncthreads();

        // S = CPo @ C^T + R ; residual
        for (int e = tid; e < 1024; e += 128) {
            int r = e >> 5, c = e & 31;
            float s = sR[r][c];
#pragma unroll
            for (int kk = 0; kk < 16; kk++) s += CPo[r][kk] * sC[c][kk];
            aug[r][c] = s;
        }
        if (tid < 32) {
            float s = as_[((long long)t * BATCH + b) * 32 + tid];
#pragma unroll
            for (int kk = 0; kk < 16; kk++) s -= sC[tid][kk] * sm_[kk];
            aug[tid][48] = s;
        }
        __syncthreads();

        // Gauss-Jordan (no pivoting; S SPD): aug[:,32:48]=S^-1 CPo, aug[:,48]=S^-1 res
        int rt = tid >> 2, ct = tid & 3;
        for (int kgj = 0; kgj < 32; kgj++) {
            if (tid < 32) colk[tid] = aug[tid][kgj];
            else if (tid < 81) rowk[tid - 32] = aug[kgj][tid - 32];
            else if (tid == 81) s_pinv = 1.f / aug[kgj][kgj];
            __syncthreads();
            if (rt != kgj) {
                float f = colk[rt] * s_pinv;
#pragma unroll 13
                for (int j = ct; j < 49; j += 4) aug[rt][j] -= f * rowk[j];
            } else {
#pragma unroll 13
                for (int j = ct; j < 49; j += 4) aug[rt][j] = rowk[j] * s_pinv;
            }
            __syncthreads();
        }

        // m_f = m + (CPo)^T y ; P_f = P - X^T CPo (then symmetrize)
        if (tid < 16) {
            float s = sm_[tid];
#pragma unroll
            for (int r = 0; r < 32; r++) s += CPo[r][tid] * aug[r][48];
            smf[tid] = s;
        }
        for (int e = tid; e < 256; e += 128) {
            int i = e >> 4, j = e & 15;
            float s = sP[i][j];
#pragma unroll
            for (int r = 0; r < 32; r++) s -= aug[r][32 + i] * CPo[r][j];
            sTmp[i][j] = s;
        }
        __syncthreads();
        for (int e = tid; e < 256; e += 128) {
            int i = e >> 4, j = e & 15;
            sPf[i][j] = 0.5f * (sTmp[i][j] + sTmp[j][i]);
        }
        __syncthreads();

        // tmp = A @ P_f
        for (int e = tid; e < 256; e += 128) {
            int i = e >> 4, j = e & 15;
            float s = 0.f;
#pragma unroll
            for (int kk = 0; kk < 16; kk++) s += sA[i][kk] * sPf[kk][j];
            sTmp[i][j] = s;
        }
        __syncthreads();
        // P_p = tmp @ A^T + Q  (into sPp unsymmetrized)
        for (int e = tid; e < 256; e += 128) {
            int i = e >> 4, j = e & 15;
            float s = sQ[i][j];
#pragma unroll
            for (int kk = 0; kk < 16; kk++) s += sTmp[i][kk] * sA[j][kk];
            sPp[i][j] = s;
        }
        __syncthreads();

        // outputs + state update
        long long orow = (long long)t * BATCH + b;
        if (tid < 16) {
            out[OFF_MEANS + orow * 16 + tid] = smf[tid];
            float s = 0.f;
#pragma unroll
            for (int kk = 0; kk < 16; kk++) s += sA[tid][kk] * smf[kk];
            out[OFF_NM + orow * 16 + tid] = s;
            sm_[tid] = s;
        }
        for (int e = tid; e < 256; e += 128) {
            int i = e >> 4, j = e & 15;
            float pf = sPf[i][j];
            float pp = 0.5f * (sPp[i][j] + sPp[j][i]);
            out[OFF_COVS + orow * 256 + e] = pf;
            out[OFF_NC + orow * 256 + e] = pp;
            sP[i][j] = pp;
        }
        __syncthreads();
    }
}

extern "C" void kernel_launch(void* const* d_in, const int* in_sizes, int n_in,
                              void* d_out, int out_size) {
    const float* as_  = (const float*)d_in[0];
    const float* AK   = (const float*)d_in[1];
    const float* CK   = (const float*)d_in[2];
    const float* QL   = (const float*)d_in[3];
    const float* RL   = (const float*)d_in[4];
    const float* Wih0 = (const float*)d_in[5];
    const float* Whh0 = (const float*)d_in[6];
    const float* bih0 = (const float*)d_in[7];
    const float* bhh0 = (const float*)d_in[8];
    const float* Wih1 = (const float*)d_in[9];
    const float* Whh1 = (const float*)d_in[10];
    const float* bih1 = (const float*)d_in[11];
    const float* bhh1 = (const float*)d_in[12];
    const float* Wlin = (const float*)d_in[13];
    const float* blin = (const float*)d_in[14];
    const float* im   = (const float*)d_in[15];
    const float* ic   = (const float*)d_in[16];
    float* out = (float*)d_out;

    prep_kernel<<<256, 256>>>(QL, RL, Wih0, Whh0, bih0, bhh0, Wih1, Whh1, bih1, bhh1);
    input_gemm0<<<TB / 64, 256>>>(as_);
    for (int k = 0; k <= T_LEN; k++)
        lstm_step<<<192, 256>>>(k);
    logits_kernel<<<TB / 4, 128>>>(Wlin, blin);
    einsum_kernel<<<8192, 256>>>(AK, CK, out);
    kalman_kernel<<<BATCH, 128>>>(as_, im, ic, out);
}

// round 13
// speedup vs baseline: 2.6621x; 2.6621x over previous
#include <cuda_runtime.h>
#include <math.h>

#define T_LEN 256
#define BATCH 512
#define ADIM 32
#define ZDIM 16
#define HID 128
#define TB (T_LEN*BATCH)
#define NBLK 128

static constexpr long long SZ_MEANS = (long long)TB * ZDIM;
static constexpr long long SZ_COVS  = (long long)TB * ZDIM * ZDIM;
static constexpr long long SZ_AS    = (long long)(T_LEN+1) * BATCH * ZDIM * ZDIM;
static constexpr long long SZ_CS    = (long long)(T_LEN+1) * BATCH * ADIM * ZDIM;
static constexpr long long OFF_MEANS = 0;
static constexpr long long OFF_COVS  = OFF_MEANS + SZ_MEANS;
static constexpr long long OFF_NM    = OFF_COVS + SZ_COVS;
static constexpr long long OFF_NC    = OFF_NM + SZ_MEANS;
static constexpr long long OFF_AS    = OFF_NC + SZ_COVS;
static constexpr long long OFF_CS    = OFF_AS + SZ_AS;

// ---------------- device scratch ----------------
__device__ float g_WT0[160 * 512];     // [k][col], col=4*j+g ; k<32 -> x dims, else h dims
__device__ float g_WT1[256 * 512];     // [k][col] ; k<128 -> h0 dims, else h1 dims
__device__ float g_h0T[2 * 128 * 512]; // [buf][hid][batch]
__device__ float g_h1T[2 * 128 * 512];
__device__ float g_h1all[(size_t)TB * 128];
__device__ float g_b0[512], g_b1[512];
__device__ float g_wall[(T_LEN + 1) * BATCH * 3];
__device__ float g_Q[ZDIM * ZDIM];
__device__ float g_R[ADIM * ADIM];
__device__ unsigned g_arrive;
__device__ volatile unsigned g_release;

// ---------------- prep ----------------
__global__ void prep_kernel(const float* __restrict__ QL, const float* __restrict__ RL,
                            const float* __restrict__ Wih0, const float* __restrict__ Whh0,
                            const float* __restrict__ bih0, const float* __restrict__ bhh0,
                            const float* __restrict__ Wih1, const float* __restrict__ Whh1,
                            const float* __restrict__ bih1, const float* __restrict__ bhh1)
{
    int gid = blockIdx.x * blockDim.x + threadIdx.x;
    int gsz = gridDim.x * blockDim.x;
    for (int i = gid; i < 160 * 512; i += gsz) {
        int k = i >> 9, c = i & 511, j = c >> 2, g = c & 3;
        g_WT0[i] = (k < 32) ? Wih0[(g * HID + j) * ADIM + k]
                            : Whh0[(g * HID + j) * HID + (k - 32)];
    }
    for (int i = gid; i < 256 * 512; i += gsz) {
        int k = i >> 9, c = i & 511, j = c >> 2, g = c & 3;
        g_WT1[i] = (k < 128) ? Wih1[(g * HID + j) * HID + k]
                             : Whh1[(g * HID + j) * HID + (k - 128)];
    }
    for (int i = gid; i < 512; i += gsz) {
        int j = i >> 2, g = i & 3, s = g * HID + j;
        g_b0[i] = bih0[s] + bhh0[s];
        g_b1[i] = bih1[s] + bhh1[s];
    }
    for (int i = gid; i < 2 * 128 * 512; i += gsz) { g_h0T[i] = 0.f; g_h1T[i] = 0.f; }
    for (int i = gid; i < BATCH * 3; i += gsz) g_wall[i] = 1.0f;
    for (int i = gid; i < ZDIM * ZDIM; i += gsz) {
        int r = i >> 4, c = i & 15;
        float s = (r == c) ? 1e-3f : 0.f;
        for (int k = 0; k < ZDIM; k++) s += QL[r * ZDIM + k] * QL[c * ZDIM + k];
        g_Q[i] = s;
    }
    for (int i = gid; i < ADIM * ADIM; i += gsz) {
        int r = i >> 5, c = i & 31;
        float s = (r == c) ? 1e-3f : 0.f;
        for (int k = 0; k < ADIM; k++) s += RL[r * ADIM + k] * RL[c * ADIM + k];
        g_R[i] = s;
    }
    if (gid == 0) { g_arrive = 0u; g_release = 0u; }
}

// ---------------- persistent fused 2-layer LSTM ----------------
// block bid: L0 tile (row0..row0+63 batch) x (col0..col0+31 gate-cols), K=160 (x|h0)
//            L1 tile same coords, K=256 (h0|h1). 8x16 tiles = 128 blocks.
#define HPITCH 68
__global__ void __launch_bounds__(256) lstm_persistent(const float* __restrict__ x)
{
    extern __shared__ float smdyn[];
    float* W0s = smdyn;                   // 160*32
    float* W1s = W0s + 160 * 32;          // 256*32
    float* HsT = W1s + 256 * 32;          // 32*HPITCH
    float* bs  = HsT + 32 * HPITCH;       // 64

    int tid = threadIdx.x;
    int bid = blockIdx.x;
    int col0 = (bid & 15) * 32;
    int row0 = (bid >> 4) * 64;
    int ty = tid >> 3, tx = tid & 7;
    int tyb = ty * 2, txc = tx * 4;
    int j = (col0 >> 2) + tx;             // absolute hidden index (0..127)

    for (int e = tid; e < 160 * 32; e += 256)
        W0s[e] = g_WT0[(e >> 5) * 512 + col0 + (e & 31)];
    for (int e = tid; e < 256 * 32; e += 256)
        W1s[e] = g_WT1[(e >> 5) * 512 + col0 + (e & 31)];
    if (tid < 32) bs[tid] = g_b0[col0 + tid];
    else if (tid < 64) bs[tid] = g_b1[col0 + tid - 32];

    float c0a = 0.f, c0b = 0.f, c1a = 0.f, c1b = 0.f;
    __syncthreads();

    for (int k = 0; k <= T_LEN; k++) {
        if (k < T_LEN) {
            float a00 = bs[txc], a01 = bs[txc+1], a02 = bs[txc+2], a03 = bs[txc+3];
            float a10 = a00, a11 = a01, a12 = a02, a13 = a03;
            const float* hprev = g_h0T + (size_t)((k + 1) & 1) * 128 * 512;
            for (int ch = 0; ch < 5; ch++) {
                __syncthreads();
                if (ch == 0) {
                    for (int e = tid; e < 2048; e += 256) {
                        int bl = e >> 5, kk = e & 31;
                        HsT[kk * HPITCH + bl] = __ldg(&x[((size_t)k * BATCH + row0 + bl) * ADIM + kk]);
                    }
                } else {
                    int kb = (ch - 1) * 32;
                    for (int q = tid; q < 512; q += 256) {
                        int kk = q >> 4, b4 = (q & 15) * 4;
                        float4 v = __ldcg((const float4*)&hprev[(kb + kk) * 512 + row0 + b4]);
                        *(float4*)&HsT[kk * HPITCH + b4] = v;
                    }
                }
                __syncthreads();
                int wb = ch * 32 * 32;
#pragma unroll
                for (int kk = 0; kk < 32; kk++) {
                    float2 av = *(const float2*)&HsT[kk * HPITCH + tyb];
                    float4 bv = *(const float4*)&W0s[wb + kk * 32 + txc];
                    a00 += av.x * bv.x; a01 += av.x * bv.y; a02 += av.x * bv.z; a03 += av.x * bv.w;
                    a10 += av.y * bv.x; a11 += av.y * bv.y; a12 += av.y * bv.z; a13 += av.y * bv.w;
                }
            }
            float* hcur = g_h0T + (size_t)(k & 1) * 128 * 512;
            {
                float ig = 1.f / (1.f + expf(-a00));
                float fg = 1.f / (1.f + expf(-a01));
                float gg = tanhf(a02);
                float og = 1.f / (1.f + expf(-a03));
                float c = fg * c0a + ig * gg; c0a = c;
                hcur[j * 512 + row0 + tyb] = og * tanhf(c);
            }
            {
                float ig = 1.f / (1.f + expf(-a10));
                float fg = 1.f / (1.f + expf(-a11));
                float gg = tanhf(a12);
                float og = 1.f / (1.f + expf(-a13));
                float c = fg * c0b + ig * gg; c0b = c;
                hcur[j * 512 + row0 + tyb + 1] = og * tanhf(c);
            }
        }
        if (k >= 1) {
            int t1 = k - 1;
            float a00 = bs[32+txc], a01 = bs[33+txc], a02 = bs[34+txc], a03 = bs[35+txc];
            float a10 = a00, a11 = a01, a12 = a02, a13 = a03;
            const float* h0in = g_h0T + (size_t)(t1 & 1) * 128 * 512;
            const float* h1in = g_h1T + (size_t)(k & 1) * 128 * 512;   // h1(k-2)
            for (int ch = 0; ch < 8; ch++) {
                __syncthreads();
                const float* src = (ch < 4) ? h0in : h1in;
                int kb = (ch & 3) * 32;
                for (int q = tid; q < 512; q += 256) {
                    int kk = q >> 4, b4 = (q & 15) * 4;
                    float4 v = __ldcg((const float4*)&src[(kb + kk) * 512 + row0 + b4]);
                    *(float4*)&HsT[kk * HPITCH + b4] = v;
                }
                __syncthreads();
                int wb = ch * 32 * 32;
#pragma unroll
                for (int kk = 0; kk < 32; kk++) {
                    float2 av = *(const float2*)&HsT[kk * HPITCH + tyb];
                    float4 bv = *(const float4*)&W1s[wb + kk * 32 + txc];
                    a00 += av.x * bv.x; a01 += av.x * bv.y; a02 += av.x * bv.z; a03 += av.x * bv.w;
                    a10 += av.y * bv.x; a11 += av.y * bv.y; a12 += av.y * bv.z; a13 += av.y * bv.w;
                }
            }
            float* h1cur = g_h1T + (size_t)((k & 1) ^ 1) * 128 * 512;
            {
                float ig = 1.f / (1.f + expf(-a00));
                float fg = 1.f / (1.f + expf(-a01));
                float gg = tanhf(a02);
                float og = 1.f / (1.f + expf(-a03));
                float c = fg * c1a + ig * gg; c1a = c;
                float h = og * tanhf(c);
                h1cur[j * 512 + row0 + tyb] = h;
                g_h1all[((size_t)t1 * 512 + row0 + tyb) * 128 + j] = h;
            }
            {
                float ig = 1.f / (1.f + expf(-a10));
                float fg = 1.f / (1.f + expf(-a11));
                float gg = tanhf(a12);
                float og = 1.f / (1.f + expf(-a13));
                float c = fg * c1b + ig * gg; c1b = c;
                float h = og * tanhf(c);
                h1cur[j * 512 + row0 + tyb + 1] = h;
                g_h1all[((size_t)t1 * 512 + row0 + tyb + 1) * 128 + j] = h;
            }
        }
        // -------- grid barrier (sense via monotone generation) --------
        __syncthreads();
        if (tid == 0) {
            __threadfence();
            unsigned gen = (unsigned)(k + 1);
            unsigned a = atomicAdd(&g_arrive, 1u);
            if (a == NBLK - 1) {
                atomicExch(&g_arrive, 0u);
                __threadfence();
                g_release = gen;
            } else {
                while (g_release < gen) { __nanosleep(32); }
            }
        }
        __syncthreads();
    }
}

// ---------------- logits + softmax ----------------
__global__ void logits_kernel(const float* __restrict__ Wlin, const float* __restrict__ blin)
{
    int row = blockIdx.x * 4 + (threadIdx.x >> 5);
    int lane = threadIdx.x & 31;
    const float* h = g_h1all + (size_t)row * HID;
    float v0 = h[lane], v1 = h[lane + 32], v2 = h[lane + 64], v3 = h[lane + 96];
    float lg[3];
#pragma unroll
    for (int kk = 0; kk < 3; kk++) {
        const float* w = Wlin + kk * HID;
        float d = v0 * w[lane] + v1 * w[lane + 32] + v2 * w[lane + 64] + v3 * w[lane + 96];
#pragma unroll
        for (int off = 16; off > 0; off >>= 1) d += __shfl_xor_sync(0xffffffffu, d, off);
        lg[kk] = d + blin[kk];
    }
    if (lane == 0) {
        float m = fmaxf(lg[0], fmaxf(lg[1], lg[2]));
        float e0 = expf(lg[0] - m), e1 = expf(lg[1] - m), e2 = expf(lg[2] - m);
        float s = 1.f / (e0 + e1 + e2);
        float* w = g_wall + ((size_t)row + BATCH) * 3;
        w[0] = e0 * s; w[1] = e1 * s; w[2] = e2 * s;
    }
}

// ---------------- einsum -> d_out ----------------
__global__ void einsum_kernel(const float* __restrict__ AK, const float* __restrict__ CK,
                              float* __restrict__ out)
{
    long long NTOT = SZ_AS + SZ_CS;
    long long stride = (long long)gridDim.x * blockDim.x;
    for (long long idx = (long long)blockIdx.x * blockDim.x + threadIdx.x; idx < NTOT; idx += stride) {
        if (idx < SZ_AS) {
            long long row = idx >> 8;
            int ij = (int)(idx & 255);
            const float* w = g_wall + row * 3;
            out[OFF_AS + idx] = w[0] * AK[ij] + w[1] * AK[256 + ij] + w[2] * AK[512 + ij];
        } else {
            long long i2 = idx - SZ_AS;
            long long row = i2 >> 9;
            int ij = (int)(i2 & 511);
            const float* w = g_wall + row * 3;
            out[OFF_CS + i2] = w[0] * CK[ij] + w[1] * CK[512 + ij] + w[2] * CK[1024 + ij];
        }
    }
}

// ---------------- Kalman: 1 block / batch element ----------------
__global__ void __launch_bounds__(128) kalman_kernel(
    const float* __restrict__ as_, const float* __restrict__ AK,
    const float* __restrict__ CK, const float* __restrict__ init_mean,
    const float* __restrict__ init_cov, float* __restrict__ out)
{
    __shared__ float sCK[3 * 512], sAK[3 * 256];
    __shared__ float sC[32 * 17], sA[16 * 17], CPo[32 * 17], sS[32 * 33], sXy[32 * 17];
    __shared__ float sP[16 * 17], sPf[16 * 17], sTmp[16 * 17], sQ[16 * 17];
    __shared__ float sR[32 * 33];
    __shared__ float sres[32], sm_[16], smf[16];

    int b = blockIdx.x, tid = threadIdx.x;
    for (int e = tid; e < 1536; e += 128) sCK[e] = CK[e];
    for (int e = tid; e < 768; e += 128) sAK[e] = AK[e];
    for (int e = tid; e < 256; e += 128) {
        sP[(e >> 4) * 17 + (e & 15)] = init_cov[e];
        sQ[(e >> 4) * 17 + (e & 15)] = g_Q[e];
    }
    for (int e = tid; e < 1024; e += 128) sR[(e >> 5) * 33 + (e & 31)] = g_R[e];
    if (tid < 16) sm_[tid] = init_mean[tid];
    __syncthreads();

    for (int t = 0; t < T_LEN; t++) {
        const float* wc = g_wall + ((size_t)t * BATCH + b) * 3;
        float w0 = wc[0], w1 = wc[1], w2 = wc[2];
        for (int e = tid; e < 512; e += 128)
            sC[(e >> 4) * 17 + (e & 15)] = w0 * sCK[e] + w1 * sCK[512 + e] + w2 * sCK[1024 + e];
        __syncthreads();
        // CPo = C @ P
        for (int e = tid; e < 512; e += 128) {
            int r = e >> 4, c = e & 15;
            float s = 0.f;
#pragma unroll
            for (int kk = 0; kk < 16; kk++) s += sC[r * 17 + kk] * sP[kk * 17 + c];
            CPo[r * 17 + c] = s;
        }
        __syncthreads();
        // S = CPo C^T + R ; res = a - C m
        for (int e = tid; e < 1024; e += 128) {
            int r = e >> 5, c = e & 31;
            float s = sR[r * 33 + c];
#pragma unroll
            for (int kk = 0; kk < 16; kk++) s += CPo[r * 17 + kk] * sC[c * 17 + kk];
            sS[r * 33 + c] = s;
        }
        if (tid < 32) {
            float s = as_[((size_t)t * BATCH + b) * 32 + tid];
#pragma unroll
            for (int kk = 0; kk < 16; kk++) s -= sC[tid * 17 + kk] * sm_[kk];
            sres[tid] = s;
        }
        __syncthreads();
        // warp 0: register Gauss-Jordan on [S | CPo | res]; warps 1-3: form A
        if (tid < 32) {
            int jn = tid;
            float cAr[32], cBr[32];
#pragma unroll
            for (int r = 0; r < 32; r++) cAr[r] = sS[r * 33 + jn];
#pragma unroll
            for (int r = 0; r < 32; r++)
                cBr[r] = (jn < 16) ? CPo[r * 17 + jn] : ((jn == 16) ? sres[r] : 0.f);
#pragma unroll
            for (int kgj = 0; kgj < 32; kgj++) {
                float pv = __shfl_sync(0xffffffffu, cAr[kgj], kgj);
                float pinv = 1.0f / pv;
                float prA = cAr[kgj] * pinv;
                float prB = cBr[kgj] * pinv;
                cAr[kgj] = prA; cBr[kgj] = prB;
#pragma unroll
                for (int r = 0; r < 32; r++) {
                    if (r == kgj) continue;
                    float cc = __shfl_sync(0xffffffffu, cAr[r], kgj);
                    cAr[r] -= cc * prA;
                    cBr[r] -= cc * prB;
                }
            }
            if (jn <= 16) {
#pragma unroll
                for (int r = 0; r < 32; r++) sXy[r * 17 + jn] = cBr[r];
            }
        } else {
            const float* wa = g_wall + ((size_t)(t + 1) * BATCH + b) * 3;
            float a0 = wa[0], a1 = wa[1], a2 = wa[2];
            for (int e = tid - 32; e < 256; e += 96)
                sA[(e >> 4) * 17 + (e & 15)] = a0 * sAK[e] + a1 * sAK[256 + e] + a2 * sAK[512 + e];
        }
        __syncthreads();
        // m_f = m + (CPo)^T y ; Tmp = P - X^T CPo
        if (tid < 16) {
            float s = sm_[tid];
#pragma unroll
            for (int r = 0; r < 32; r++) s += CPo[r * 17 + tid] * sXy[r * 17 + 16];
            smf[tid] = s;
        }
        for (int e = tid; e < 256; e += 128) {
            int i = e >> 4, jj = e & 15;
            float s = sP[i * 17 + jj];
#pragma unroll
            for (int r = 0; r < 32; r++) s -= sXy[r * 17 + i] * CPo[r * 17 + jj];
            sTmp[i * 17 + jj] = s;
        }
        __syncthreads();
        for (int e = tid; e < 256; e += 128) {
            int i = e >> 4, jj = e & 15;
            sPf[i * 17 + jj] = 0.5f * (sTmp[i * 17 + jj] + sTmp[jj * 17 + i]);
        }
        __syncthreads();
        // Tmp = A @ Pf
        for (int e = tid; e < 256; e += 128) {
            int i = e >> 4, jj = e & 15;
            float s = 0.f;
#pragma unroll
            for (int kk = 0; kk < 16; kk++) s += sA[i * 17 + kk] * sPf[kk * 17 + jj];
            sTmp[i * 17 + jj] = s;
        }
        __syncthreads();
        // Pp (unsym) = Tmp A^T + Q into CPo region
        for (int e = tid; e < 256; e += 128) {
            int i = e >> 4, jj = e & 15;
            float s = sQ[i * 17 + jj];
#pragma unroll
            for (int kk = 0; kk < 16; kk++) s += sTmp[i * 17 + kk] * sA[jj * 17 + kk];
            CPo[i * 17 + jj] = s;
        }
        __syncthreads();
        long long orow = (long long)t * BATCH + b;
        if (tid < 16) {
            out[OFF_MEANS + orow * 16 + tid] = smf[tid];
            float s = 0.f;
#pragma unroll
            for (int kk = 0; kk < 16; kk++) s += sA[tid * 17 + kk] * smf[kk];
            out[OFF_NM + orow * 16 + tid] = s;
            sm_[tid] = s;
        }
        for (int e = tid; e < 256; e += 128) {
            int i = e >> 4, jj = e & 15;
            float pp = 0.5f * (CPo[i * 17 + jj] + CPo[jj * 17 + i]);
            out[OFF_COVS + orow * 256 + e] = sPf[i * 17 + jj];
            out[OFF_NC + orow * 256 + e] = pp;
            sP[i * 17 + jj] = pp;
        }
        __syncthreads();
    }
}

extern "C" void kernel_launch(void* const* d_in, const int* in_sizes, int n_in,
                              void* d_out, int out_size) {
    const float* as_  = (const float*)d_in[0];
    const float* AK   = (const float*)d_in[1];
    const float* CK   = (const float*)d_in[2];
    const float* QL   = (const float*)d_in[3];
    const float* RL   = (const float*)d_in[4];
    const float* Wih0 = (const float*)d_in[5];
    const float* Whh0 = (const float*)d_in[6];
    const float* bih0 = (const float*)d_in[7];
    const float* bhh0 = (const float*)d_in[8];
    const float* Wih1 = (const float*)d_in[9];
    const float* Whh1 = (const float*)d_in[10];
    const float* bih1 = (const float*)d_in[11];
    const float* bhh1 = (const float*)d_in[12];
    const float* Wlin = (const float*)d_in[13];
    const float* blin = (const float*)d_in[14];
    const float* im   = (const float*)d_in[15];
    const float* ic   = (const float*)d_in[16];
    float* out = (float*)d_out;

    int smem = (160 * 32 + 256 * 32 + 32 * HPITCH + 64) * 4;
    cudaFuncSetAttribute(lstm_persistent, cudaFuncAttributeMaxDynamicSharedMemorySize, smem);

    prep_kernel<<<256, 256>>>(QL, RL, Wih0, Whh0, bih0, bhh0, Wih1, Whh1, bih1, bhh1);
    lstm_persistent<<<NBLK, 256, smem>>>(as_);
    logits_kernel<<<TB / 4, 128>>>(Wlin, blin);
    einsum_kernel<<<8192, 256>>>(AK, CK, out);
    kalman_kernel<<<BATCH, 128>>>(as_, AK, CK, im, ic, out);
}

// round 14
// speedup vs baseline: 3.5133x; 1.3198x over previous
#include <cuda_runtime.h>
#include <math.h>

#define T_LEN 256
#define BATCH 512
#define ADIM 32
#define ZDIM 16
#define HID 128
#define TB (T_LEN*BATCH)
#define NBLK 128
#define HPITCH 68

static constexpr long long SZ_MEANS = (long long)TB * ZDIM;
static constexpr long long SZ_COVS  = (long long)TB * ZDIM * ZDIM;
static constexpr long long SZ_AS    = (long long)(T_LEN+1) * BATCH * ZDIM * ZDIM;
static constexpr long long SZ_CS    = (long long)(T_LEN+1) * BATCH * ADIM * ZDIM;
static constexpr long long OFF_MEANS = 0;
static constexpr long long OFF_COVS  = OFF_MEANS + SZ_MEANS;
static constexpr long long OFF_NM    = OFF_COVS + SZ_COVS;
static constexpr long long OFF_NC    = OFF_NM + SZ_MEANS;
static constexpr long long OFF_AS    = OFF_NC + SZ_COVS;
static constexpr long long OFF_CS    = OFF_AS + SZ_AS;

// ---------------- device scratch ----------------
__device__ float g_WT0[160 * 512];
__device__ float g_WT1[256 * 512];
__device__ float g_h0T[2 * 128 * 512];
__device__ float g_h1T[2 * 128 * 512];
__device__ float g_h1all[(size_t)TB * 128];
__device__ float g_b0[512], g_b1[512];
__device__ float g_wall[(T_LEN + 1) * BATCH * 3];
__device__ float g_Q[ZDIM * ZDIM];
__device__ float g_R[ADIM * ADIM];
__device__ unsigned g_arrive;
__device__ volatile unsigned g_release;

// ---------------- prep ----------------
__global__ void prep_kernel(const float* __restrict__ QL, const float* __restrict__ RL,
                            const float* __restrict__ Wih0, const float* __restrict__ Whh0,
                            const float* __restrict__ bih0, const float* __restrict__ bhh0,
                            const float* __restrict__ Wih1, const float* __restrict__ Whh1,
                            const float* __restrict__ bih1, const float* __restrict__ bhh1)
{
    int gid = blockIdx.x * blockDim.x + threadIdx.x;
    int gsz = gridDim.x * blockDim.x;
    for (int i = gid; i < 160 * 512; i += gsz) {
        int k = i >> 9, c = i & 511, j = c >> 2, g = c & 3;
        g_WT0[i] = (k < 32) ? Wih0[(g * HID + j) * ADIM + k]
                            : Whh0[(g * HID + j) * HID + (k - 32)];
    }
    for (int i = gid; i < 256 * 512; i += gsz) {
        int k = i >> 9, c = i & 511, j = c >> 2, g = c & 3;
        g_WT1[i] = (k < 128) ? Wih1[(g * HID + j) * HID + k]
                             : Whh1[(g * HID + j) * HID + (k - 128)];
    }
    for (int i = gid; i < 512; i += gsz) {
        int j = i >> 2, g = i & 3, s = g * HID + j;
        g_b0[i] = bih0[s] + bhh0[s];
        g_b1[i] = bih1[s] + bhh1[s];
    }
    for (int i = gid; i < 2 * 128 * 512; i += gsz) { g_h0T[i] = 0.f; g_h1T[i] = 0.f; }
    for (int i = gid; i < BATCH * 3; i += gsz) g_wall[i] = 1.0f;
    for (int i = gid; i < ZDIM * ZDIM; i += gsz) {
        int r = i >> 4, c = i & 15;
        float s = (r == c) ? 1e-3f : 0.f;
        for (int k = 0; k < ZDIM; k++) s += QL[r * ZDIM + k] * QL[c * ZDIM + k];
        g_Q[i] = s;
    }
    for (int i = gid; i < ADIM * ADIM; i += gsz) {
        int r = i >> 5, c = i & 31;
        float s = (r == c) ? 1e-3f : 0.f;
        for (int k = 0; k < ADIM; k++) s += RL[r * ADIM + k] * RL[c * ADIM + k];
        g_R[i] = s;
    }
    if (gid == 0) { g_arrive = 0u; g_release = 0u; }
}

// ---------------- persistent fused 2-layer LSTM ----------------
__global__ void __launch_bounds__(256) lstm_persistent(const float* __restrict__ x)
{
    extern __shared__ float smdyn[];
    float* W0s = smdyn;               // 5120
    float* W1s = W0s + 5120;          // 8192
    float* HsT = W1s + 8192;          // 2*2176 (double buffer)
    float* bs  = HsT + 4352;          // 64

    int tid = threadIdx.x;
    int bid = blockIdx.x;
    int col0 = (bid & 15) * 32;
    int row0 = (bid >> 4) * 64;
    int ty = tid >> 3, tx = tid & 7;
    int tyb = ty * 2, txc = tx * 4;
    int j = (col0 >> 2) + tx;

    for (int e = tid; e < 5120; e += 256)
        W0s[e] = g_WT0[(e >> 5) * 512 + col0 + (e & 31)];
    for (int e = tid; e < 8192; e += 256)
        W1s[e] = g_WT1[(e >> 5) * 512 + col0 + (e & 31)];
    if (tid < 32) bs[tid] = g_b0[col0 + tid];
    else if (tid < 64) bs[tid] = g_b1[col0 + tid - 32];

    int kk0 = tid >> 4, b40 = (tid & 15) * 4;
    int q1x = tid + 256;
    int kk1 = q1x >> 4, b41 = (q1x & 15) * 4;

    float c0a = 0.f, c0b = 0.f, c1a = 0.f, c1b = 0.f;
    __syncthreads();

    for (int k = 0; k <= T_LEN; k++) {
        if (k < T_LEN) {
            float a00 = bs[txc], a01 = bs[txc+1], a02 = bs[txc+2], a03 = bs[txc+3];
            float a10 = a00, a11 = a01, a12 = a02, a13 = a03;
            const float* hprev = g_h0T + (size_t)((k + 1) & 1) * 65536;
            float xr[8];
            size_t xbase = (size_t)k * BATCH * ADIM;
#pragma unroll
            for (int q = 0; q < 8; q++) {
                int e = tid + q * 256;
                xr[q] = __ldg(&x[xbase + (size_t)(row0 + (e >> 5)) * ADIM + (e & 31)]);
            }
            float4 p0, p1;
            for (int ch = 0; ch < 5; ch++) {
                float* buf = HsT + (ch & 1) * 2176;
                if (ch == 0) {
#pragma unroll
                    for (int q = 0; q < 8; q++) {
                        int e = tid + q * 256;
                        buf[(e & 31) * HPITCH + (e >> 5)] = xr[q];
                    }
                } else {
                    *(float4*)&buf[kk0 * HPITCH + b40] = p0;
                    *(float4*)&buf[kk1 * HPITCH + b41] = p1;
                }
                if (ch < 4) {
                    int kb = ch * 32;
                    p0 = __ldcg((const float4*)&hprev[(kb + kk0) * 512 + row0 + b40]);
                    p1 = __ldcg((const float4*)&hprev[(kb + kk1) * 512 + row0 + b41]);
                }
                __syncthreads();
                int wb = ch * 1024;
#pragma unroll
                for (int kk = 0; kk < 32; kk++) {
                    float2 av = *(const float2*)&buf[kk * HPITCH + tyb];
                    float4 bv = *(const float4*)&W0s[wb + kk * 32 + txc];
                    a00 += av.x * bv.x; a01 += av.x * bv.y; a02 += av.x * bv.z; a03 += av.x * bv.w;
                    a10 += av.y * bv.x; a11 += av.y * bv.y; a12 += av.y * bv.z; a13 += av.y * bv.w;
                }
            }
            __syncthreads();  // HsT free before L1 reuses buf0
            float* hcur = g_h0T + (size_t)(k & 1) * 65536;
            {
                float ig = 1.f / (1.f + expf(-a00));
                float fg = 1.f / (1.f + expf(-a01));
                float gg = tanhf(a02);
                float og = 1.f / (1.f + expf(-a03));
                float c = fg * c0a + ig * gg; c0a = c;
                hcur[j * 512 + row0 + tyb] = og * tanhf(c);
            }
            {
                float ig = 1.f / (1.f + expf(-a10));
                float fg = 1.f / (1.f + expf(-a11));
                float gg = tanhf(a12);
                float og = 1.f / (1.f + expf(-a13));
                float c = fg * c0b + ig * gg; c0b = c;
                hcur[j * 512 + row0 + tyb + 1] = og * tanhf(c);
            }
        }
        if (k >= 1) {
            int t1 = k - 1;
            float a00 = bs[32+txc], a01 = bs[33+txc], a02 = bs[34+txc], a03 = bs[35+txc];
            float a10 = a00, a11 = a01, a12 = a02, a13 = a03;
            const float* h0in = g_h0T + (size_t)(t1 & 1) * 65536;
            const float* h1in = g_h1T + (size_t)(k & 1) * 65536;   // h1(k-2)
            float4 p0 = __ldcg((const float4*)&h0in[kk0 * 512 + row0 + b40]);
            float4 p1 = __ldcg((const float4*)&h0in[kk1 * 512 + row0 + b41]);
            for (int ch = 0; ch < 8; ch++) {
                float* buf = HsT + (ch & 1) * 2176;
                *(float4*)&buf[kk0 * HPITCH + b40] = p0;
                *(float4*)&buf[kk1 * HPITCH + b41] = p1;
                if (ch < 7) {
                    const float* src = (ch + 1 < 4) ? h0in : h1in;
                    int kb = ((ch + 1) & 3) * 32;
                    p0 = __ldcg((const float4*)&src[(kb + kk0) * 512 + row0 + b40]);
                    p1 = __ldcg((const float4*)&src[(kb + kk1) * 512 + row0 + b41]);
                }
                __syncthreads();
                int wb = ch * 1024;
#pragma unroll
                for (int kk = 0; kk < 32; kk++) {
                    float2 av = *(const float2*)&buf[kk * HPITCH + tyb];
                    float4 bv = *(const float4*)&W1s[wb + kk * 32 + txc];
                    a00 += av.x * bv.x; a01 += av.x * bv.y; a02 += av.x * bv.z; a03 += av.x * bv.w;
                    a10 += av.y * bv.x; a11 += av.y * bv.y; a12 += av.y * bv.z; a13 += av.y * bv.w;
                }
            }
            float* h1cur = g_h1T + (size_t)((k & 1) ^ 1) * 65536;
            {
                float ig = 1.f / (1.f + expf(-a00));
                float fg = 1.f / (1.f + expf(-a01));
                float gg = tanhf(a02);
                float og = 1.f / (1.f + expf(-a03));
                float c = fg * c1a + ig * gg; c1a = c;
                float h = og * tanhf(c);
                h1cur[j * 512 + row0 + tyb] = h;
                g_h1all[((size_t)t1 * 512 + row0 + tyb) * 128 + j] = h;
            }
            {
                float ig = 1.f / (1.f + expf(-a10));
                float fg = 1.f / (1.f + expf(-a11));
                float gg = tanhf(a12);
                float og = 1.f / (1.f + expf(-a13));
                float c = fg * c1b + ig * gg; c1b = c;
                float h = og * tanhf(c);
                h1cur[j * 512 + row0 + tyb + 1] = h;
                g_h1all[((size_t)t1 * 512 + row0 + tyb + 1) * 128 + j] = h;
            }
        }
        // -------- grid barrier --------
        __syncthreads();
        if (tid == 0) {
            __threadfence();
            unsigned gen = (unsigned)(k + 1);
            unsigned a = atomicAdd(&g_arrive, 1u);
            if (a == NBLK - 1) {
                atomicExch(&g_arrive, 0u);
                __threadfence();
                g_release = gen;
            } else {
                while (g_release < gen) { }
            }
        }
        __syncthreads();
    }
}

// ---------------- logits + softmax ----------------
__global__ void logits_kernel(const float* __restrict__ Wlin, const float* __restrict__ blin)
{
    int row = blockIdx.x * 4 + (threadIdx.x >> 5);
    int lane = threadIdx.x & 31;
    const float* h = g_h1all + (size_t)row * HID;
    float v0 = h[lane], v1 = h[lane + 32], v2 = h[lane + 64], v3 = h[lane + 96];
    float lg[3];
#pragma unroll
    for (int kk = 0; kk < 3; kk++) {
        const float* w = Wlin + kk * HID;
        float d = v0 * w[lane] + v1 * w[lane + 32] + v2 * w[lane + 64] + v3 * w[lane + 96];
#pragma unroll
        for (int off = 16; off > 0; off >>= 1) d += __shfl_xor_sync(0xffffffffu, d, off);
        lg[kk] = d + blin[kk];
    }
    if (lane == 0) {
        float m = fmaxf(lg[0], fmaxf(lg[1], lg[2]));
        float e0 = expf(lg[0] - m), e1 = expf(lg[1] - m), e2 = expf(lg[2] - m);
        float s = 1.f / (e0 + e1 + e2);
        float* w = g_wall + ((size_t)row + BATCH) * 3;
        w[0] = e0 * s; w[1] = e1 * s; w[2] = e2 * s;
    }
}

// ---------------- edge rows: AS row 0, CS row T ----------------
__global__ void edge_kernel(const float* __restrict__ AK, const float* __restrict__ CK,
                            float* __restrict__ out)
{
    int NTOT = 512 * 256 + 512 * 512;
    int stride = gridDim.x * blockDim.x;
    for (int idx = blockIdx.x * blockDim.x + threadIdx.x; idx < NTOT; idx += stride) {
        if (idx < 131072) {
            int b = idx >> 8, e = idx & 255;
            out[OFF_AS + (size_t)b * 256 + e] = AK[e] + AK[256 + e] + AK[512 + e];
        } else {
            int i2 = idx - 131072;
            int b = i2 >> 9, e = i2 & 511;
            const float* w = g_wall + ((size_t)T_LEN * BATCH + b) * 3;
            out[OFF_CS + ((size_t)T_LEN * BATCH + b) * 512 + e] =
                w[0] * CK[e] + w[1] * CK[512 + e] + w[2] * CK[1024 + e];
        }
    }
}

// ---------------- Kalman: 1 WARP per batch element, no block syncs ----------------
__global__ void __launch_bounds__(128) kalman_kernel(
    const float* __restrict__ as_, const float* __restrict__ AK,
    const float* __restrict__ CK, const float* __restrict__ im,
    const float* __restrict__ ic, float* __restrict__ out)
{
    extern __shared__ float sm[];
    float* sCK = sm;                 // 3*32*17 = 1632 (pitch 17)
    float* sAK = sCK + 1632;         // 3*16*17 = 816
    float* sR  = sAK + 816;          // 32*33 = 1056
    float* sQ  = sR + 1056;          // 16*17 = 272
    float* wsAll = sQ + 272;         // per warp: 2176

    int tid = threadIdx.x, wid = tid >> 5, l = tid & 31;
    int b = blockIdx.x * 4 + wid;
    float* P  = wsAll + wid * 2176;  // 16*17
    float* CP = P + 272;             // 32*17
    float* X  = CP + 544;            // 32*17
    float* Pf = X + 544;             // 16*17
    float* A  = Pf + 272;            // 16*17
    float* Tm = A + 272;             // 16*17

    for (int e = tid; e < 1536; e += 128) {
        int kk = e >> 9, rem = e & 511;
        sCK[kk * 544 + (rem >> 4) * 17 + (rem & 15)] = CK[e];
    }
    for (int e = tid; e < 768; e += 128) {
        int kk = e >> 8, rem = e & 255;
        sAK[kk * 272 + (rem >> 4) * 17 + (rem & 15)] = AK[e];
    }
    for (int e = tid; e < 1024; e += 128) sR[(e >> 5) * 33 + (e & 31)] = g_R[e];
    for (int e = tid; e < 256; e += 128) sQ[(e >> 4) * 17 + (e & 15)] = g_Q[e];
    for (int e = l; e < 256; e += 32) P[(e >> 4) * 17 + (e & 15)] = ic[e];
    float m[16];
#pragma unroll
    for (int k = 0; k < 16; k++) m[k] = im[k];
    __syncthreads();

    int i_ = l >> 1, j0 = (l & 1) * 8;

    for (int t = 0; t < T_LEN; t++) {
        size_t row = (size_t)t * BATCH + b;
        const float* wl = g_wall + row * 3;
        float w0 = wl[0], w1 = wl[1], w2 = wl[2];
        // C row l, write CS output
        float c[16];
#pragma unroll
        for (int k = 0; k < 16; k++)
            c[k] = w0 * sCK[l*17+k] + w1 * sCK[544 + l*17+k] + w2 * sCK[1088 + l*17+k];
        {
            float4* dst = (float4*)(out + OFF_CS + row * 512 + l * 16);
            dst[0] = make_float4(c[0], c[1], c[2], c[3]);
            dst[1] = make_float4(c[4], c[5], c[6], c[7]);
            dst[2] = make_float4(c[8], c[9], c[10], c[11]);
            dst[3] = make_float4(c[12], c[13], c[14], c[15]);
        }
        // CPo row l
        float cp[16];
#pragma unroll
        for (int jj = 0; jj < 16; jj++) cp[jj] = 0.f;
#pragma unroll
        for (int k = 0; k < 16; k++) {
            float ck = c[k];
#pragma unroll
            for (int jj = 0; jj < 16; jj++) cp[jj] += ck * P[k*17+jj];
        }
#pragma unroll
        for (int jj = 0; jj < 16; jj++) CP[l*17+jj] = cp[jj];
        // residual
        float res = as_[row * 32 + l];
#pragma unroll
        for (int k = 0; k < 16; k++) res -= c[k] * m[k];
        __syncwarp();
        // S column l (lane l holds col l), B columns
        float Ac[32], Bc[32];
#pragma unroll
        for (int r = 0; r < 32; r++) {
            float s = sR[r*33 + l];
#pragma unroll
            for (int k = 0; k < 16; k++) s += CP[r*17+k] * c[k];
            Ac[r] = s;
        }
#pragma unroll
        for (int r = 0; r < 32; r++) Bc[r] = (l < 16) ? CP[r*17+l] : 0.f;
#pragma unroll
        for (int r = 0; r < 32; r++) {
            float rr = __shfl_sync(0xffffffffu, res, r);
            if (l == 16) Bc[r] = rr;
        }
        // Gauss-Jordan (S SPD, no pivoting), column-per-lane
#pragma unroll
        for (int kg = 0; kg < 32; kg++) {
            float pv = __shfl_sync(0xffffffffu, Ac[kg], kg);
            float pinv = __fdividef(1.0f, pv);
            float prA = Ac[kg] * pinv;
            float prB = Bc[kg] * pinv;
            Ac[kg] = prA; Bc[kg] = prB;
#pragma unroll
            for (int r = 0; r < 32; r++) {
                if (r == kg) continue;
                float cc = __shfl_sync(0xffffffffu, Ac[r], kg);
                Ac[r] -= cc * prA;
                Bc[r] -= cc * prB;
            }
        }
        if (l <= 16) {
#pragma unroll
            for (int r = 0; r < 32; r++) X[r*17 + l] = Bc[r];
        }
        __syncwarp();
        // m_f
        float mf = 0.f;
        if (l < 16) {
            mf = m[l];
#pragma unroll
            for (int r = 0; r < 32; r++) mf += CP[r*17+l] * X[r*17+16];
            out[OFF_MEANS + row * 16 + l] = mf;
        }
#pragma unroll
        for (int k = 0; k < 16; k++) m[k] = __shfl_sync(0xffffffffu, mf, k);
        // Pf unsym -> Tm (8 elems/lane)
        {
            float v[8];
#pragma unroll
            for (int jj = 0; jj < 8; jj++) {
                int jc = j0 + jj;
                float s = P[i_*17+jc];
#pragma unroll
                for (int r = 0; r < 32; r++) s -= X[r*17+i_] * CP[r*17+jc];
                v[jj] = s;
            }
#pragma unroll
            for (int jj = 0; jj < 8; jj++) Tm[i_*17+j0+jj] = v[jj];
        }
        __syncwarp();
        // sym Pf + covs out ; A formation + AS(t+1) out
        const float* wa = g_wall + ((size_t)(t + 1) * BATCH + b) * 3;
        float a0 = wa[0], a1 = wa[1], a2 = wa[2];
        {
            float v[8], u[8];
#pragma unroll
            for (int jj = 0; jj < 8; jj++) {
                int jc = j0 + jj;
                v[jj] = 0.5f * (Tm[i_*17+jc] + Tm[jc*17+i_]);
                Pf[i_*17+jc] = v[jj];
                u[jj] = a0 * sAK[i_*17+jc] + a1 * sAK[272 + i_*17+jc] + a2 * sAK[544 + i_*17+jc];
                A[i_*17+jc] = u[jj];
            }
            float4* d1 = (float4*)(out + OFF_COVS + row * 256 + l * 8);
            d1[0] = make_float4(v[0], v[1], v[2], v[3]);
            d1[1] = make_float4(v[4], v[5], v[6], v[7]);
            float4* d2 = (float4*)(out + OFF_AS + ((size_t)(t + 1) * BATCH + b) * 256 + l * 8);
            d2[0] = make_float4(u[0], u[1], u[2], u[3]);
            d2[1] = make_float4(u[4], u[5], u[6], u[7]);
        }
        __syncwarp();
        // m_p
        float mp = 0.f;
        if (l < 16) {
#pragma unroll
            for (int k = 0; k < 16; k++) mp += A[l*17+k] * m[k];
            out[OFF_NM + row * 16 + l] = mp;
        }
        // Tm = A @ Pf
        {
            float v[8];
#pragma unroll
            for (int jj = 0; jj < 8; jj++) {
                int jc = j0 + jj;
                float s = 0.f;
#pragma unroll
                for (int k = 0; k < 16; k++) s += A[i_*17+k] * Pf[k*17+jc];
                v[jj] = s;
            }
#pragma unroll
            for (int jj = 0; jj < 8; jj++) Tm[i_*17+j0+jj] = v[jj];
        }
#pragma unroll
        for (int k = 0; k < 16; k++) m[k] = __shfl_sync(0xffffffffu, mp, k);
        __syncwarp();
        // Pp unsym -> X (reuse)
        {
            float v[8];
#pragma unroll
            for (int jj = 0; jj < 8; jj++) {
                int jc = j0 + jj;
                float s = sQ[i_*17+jc];
#pragma unroll
                for (int k = 0; k < 16; k++) s += Tm[i_*17+k] * A[jc*17+k];
                v[jj] = s;
            }
#pragma unroll
            for (int jj = 0; jj < 8; jj++) X[i_*17+j0+jj] = v[jj];
        }
        __syncwarp();
        // sym Pp -> P, NC out
        {
            float v[8];
#pragma unroll
            for (int jj = 0; jj < 8; jj++) {
                int jc = j0 + jj;
                v[jj] = 0.5f * (X[i_*17+jc] + X[jc*17+i_]);
                P[i_*17+jc] = v[jj];
            }
            float4* d = (float4*)(out + OFF_NC + row * 256 + l * 8);
            d[0] = make_float4(v[0], v[1], v[2], v[3]);
            d[1] = make_float4(v[4], v[5], v[6], v[7]);
        }
        __syncwarp();
    }
}

extern "C" void kernel_launch(void* const* d_in, const int* in_sizes, int n_in,
                              void* d_out, int out_size) {
    const float* as_  = (const float*)d_in[0];
    const float* AK   = (const float*)d_in[1];
    const float* CK   = (const float*)d_in[2];
    const float* QL   = (const float*)d_in[3];
    const float* RL   = (const float*)d_in[4];
    const float* Wih0 = (const float*)d_in[5];
    const float* Whh0 = (const float*)d_in[6];
    const float* bih0 = (const float*)d_in[7];
    const float* bhh0 = (const float*)d_in[8];
    const float* Wih1 = (const float*)d_in[9];
    const float* Whh1 = (const float*)d_in[10];
    const float* bih1 = (const float*)d_in[11];
    const float* bhh1 = (const float*)d_in[12];
    const float* Wlin = (const float*)d_in[13];
    const float* blin = (const float*)d_in[14];
    const float* im   = (const float*)d_in[15];
    const float* ic   = (const float*)d_in[16];
    float* out = (float*)d_out;

    int smemL = (5120 + 8192 + 4352 + 64) * 4;
    int smemK = (1632 + 816 + 1056 + 272 + 4 * 2176) * 4;
    cudaFuncSetAttribute(lstm_persistent, cudaFuncAttributeMaxDynamicSharedMemorySize, smemL);
    cudaFuncSetAttribute(kalman_kernel, cudaFuncAttributeMaxDynamicSharedMemorySize, smemK);

    prep_kernel<<<256, 256>>>(QL, RL, Wih0, Whh0, bih0, bhh0, Wih1, Whh1, bih1, bhh1);
    lstm_persistent<<<NBLK, 256, smemL>>>(as_);
    logits_kernel<<<TB / 4, 128>>>(Wlin, blin);
    edge_kernel<<<1536, 256>>>(AK, CK, out);
    kalman_kernel<<<BATCH / 4, 128, smemK>>>(as_, AK, CK, im, ic, out);
}